// round 3
// baseline (speedup 1.0000x reference)
#include <cuda_runtime.h>
#include <cuda_bf16.h>

// Problem constants
#define NN 10000
#define DD 128
#define NDSZ (NN * DD)

// Scratch (no allocations allowed; referenced directly from device code —
// NO host-side API calls in kernel_launch besides kernel launches)
__device__ float g_qkvs[4 * NDSZ];   // Q, K, V, S(=h@Ws+bs)
__device__ float g_h[NDSZ];          // hidden after layer 0
__device__ int   g_rowptr[NN + 1];

// ---------------------------------------------------------------------------
// row_ptr: edges sorted by src; rowptr[i] = first index with src[e] >= i
// ---------------------------------------------------------------------------
__global__ void build_rowptr_kernel(const int* __restrict__ src, int E) {
    int i = blockIdx.x * blockDim.x + threadIdx.x;
    if (i > NN) return;
    int lo = 0, hi = E;
    while (lo < hi) {
        int mid = (lo + hi) >> 1;
        if (src[mid] < i) lo = mid + 1; else hi = mid;
    }
    g_rowptr[i] = lo;
}

// ---------------------------------------------------------------------------
// Fused projection GEMM: g_qkvs[m] = h @ W_m + b_m for m in {q,k,v,s}
// A: [NN,128] row-major. Each W: [L,128,128] (in-dim major). M=10000, N=512, K=128
// Block tile 64x64, BK=16, 256 threads, 4x4 microtile.
// blockIdx.y in [0,8): matrix = y>>1, 64-col half = y&1.
// ---------------------------------------------------------------------------
#define BM 64
#define BN 64
#define BK 16

__global__ __launch_bounds__(256)
void gemm_qkvs_kernel(const float* __restrict__ A,
                      const float* __restrict__ Wq, const float* __restrict__ Wk,
                      const float* __restrict__ Wv, const float* __restrict__ Ws,
                      const float* __restrict__ bq, const float* __restrict__ bk,
                      const float* __restrict__ bv, const float* __restrict__ bs,
                      int layer) {
    __shared__ float Asm[BK][BM + 4];
    __shared__ float Bsm[BK][BN];

    const int mtx = blockIdx.y >> 1;
    const float* W = (mtx == 0 ? Wq : mtx == 1 ? Wk : mtx == 2 ? Wv : Ws)
                     + (size_t)layer * DD * DD;
    const float* bias = (mtx == 0 ? bq : mtx == 1 ? bk : mtx == 2 ? bv : bs)
                        + layer * DD;
    const int colbase = (blockIdx.y & 1) * BN;
    const int rowbase = blockIdx.x * BM;

    const int tid = threadIdx.x;
    const int tx = tid & 15;        // 16 col-tiles
    const int ty = tid >> 4;        // 16 row-tiles

    float acc[4][4] = {};

    for (int k0 = 0; k0 < DD; k0 += BK) {
        // Load A tile 64x16 transposed into shared
        #pragma unroll
        for (int r = 0; r < 4; ++r) {
            int row = (tid >> 4) + r * 16;
            int grow = rowbase + row;
            float v = (grow < NN) ? A[(size_t)grow * DD + k0 + (tid & 15)] : 0.f;
            Asm[tid & 15][row] = v;
        }
        // Load B tile 16x64
        #pragma unroll
        for (int r = 0; r < 4; ++r) {
            int kk = (tid >> 6) + r * 4;
            int col = tid & 63;
            Bsm[kk][col] = W[(size_t)(k0 + kk) * DD + colbase + col];
        }
        __syncthreads();

        #pragma unroll
        for (int kk = 0; kk < BK; ++kk) {
            float a[4], b[4];
            *(float4*)a = *(const float4*)&Asm[kk][ty * 4];
            *(float4*)b = *(const float4*)&Bsm[kk][tx * 4];
            #pragma unroll
            for (int i2 = 0; i2 < 4; ++i2)
                #pragma unroll
                for (int j2 = 0; j2 < 4; ++j2)
                    acc[i2][j2] += a[i2] * b[j2];
        }
        __syncthreads();
    }

    // Epilogue: add bias, write to g_qkvs[mtx*NDSZ + row*128 + col]
    float4 bvec;
    {
        const float* bp = bias + colbase + tx * 4;
        bvec.x = bp[0]; bvec.y = bp[1]; bvec.z = bp[2]; bvec.w = bp[3];
    }
    #pragma unroll
    for (int i2 = 0; i2 < 4; ++i2) {
        int grow = rowbase + ty * 4 + i2;
        if (grow < NN) {
            float4 o;
            o.x = acc[i2][0] + bvec.x;
            o.y = acc[i2][1] + bvec.y;
            o.z = acc[i2][2] + bvec.z;
            o.w = acc[i2][3] + bvec.w;
            *(float4*)&g_qkvs[(size_t)mtx * NDSZ + (size_t)grow * DD + colbase + tx * 4] = o;
        }
    }
}

// ---------------------------------------------------------------------------
// Attention: one warp per destination node, online softmax over incoming edges.
// Graph is symmetric, so incoming neighbors of i = dst[e] for e in rowptr[i]..rowptr[i+1]
// (the contiguous block where src == i).
// Lane l holds dims [4l, 4l+4); head = l>>2; per-head dot via shfl_xor(1),(2).
// out = h + agg + S ; optional ReLU.
// ---------------------------------------------------------------------------
__global__ __launch_bounds__(256)
void attn_kernel(const float* __restrict__ h,
                 const int* __restrict__ nbr,      // dst array of edge list
                 float* __restrict__ out, int do_relu) {
    int gwarp = (blockIdx.x * blockDim.x + threadIdx.x) >> 5;
    if (gwarp >= NN) return;
    const int lane = threadIdx.x & 31;
    const int i = gwarp;

    const float* Q = g_qkvs;
    const float* K = g_qkvs + NDSZ;
    const float* V = g_qkvs + 2 * NDSZ;
    const float* S = g_qkvs + 3 * NDSZ;

    // load q and fold in 1/sqrt(C) = 0.25
    float4 q4 = *(const float4*)&Q[(size_t)i * DD + lane * 4];
    q4.x *= 0.25f; q4.y *= 0.25f; q4.z *= 0.25f; q4.w *= 0.25f;

    float m = -1e30f;
    float z = 0.f;
    float4 acc = make_float4(0.f, 0.f, 0.f, 0.f);

    const int e0 = g_rowptr[i];
    const int e1 = g_rowptr[i + 1];

    int j = (e0 < e1) ? nbr[e0] : 0;      // prefetched neighbor index
    for (int e = e0; e < e1; ++e) {
        int jn = (e + 1 < e1) ? nbr[e + 1] : 0;   // prefetch next index
        float4 k4 = *(const float4*)&K[(size_t)j * DD + lane * 4];
        float4 v4 = *(const float4*)&V[(size_t)j * DD + lane * 4];
        float d = q4.x * k4.x + q4.y * k4.y + q4.z * k4.z + q4.w * k4.w;
        // reduce within the 4-lane head group
        d += __shfl_xor_sync(0xFFFFFFFFu, d, 1);
        d += __shfl_xor_sync(0xFFFFFFFFu, d, 2);

        float nm = fmaxf(m, d);
        float scale = __expf(m - nm);    // 0 on first edge (m=-1e30)
        float p = __expf(d - nm);
        z = z * scale + p;

        acc.x = acc.x * scale + p * v4.x;
        acc.y = acc.y * scale + p * v4.y;
        acc.z = acc.z * scale + p * v4.z;
        acc.w = acc.w * scale + p * v4.w;
        m = nm;
        j = jn;
    }

    float inv = 1.f / z;
    float4 h4 = *(const float4*)&h[(size_t)i * DD + lane * 4];
    float4 s4 = *(const float4*)&S[(size_t)i * DD + lane * 4];
    float4 o;
    o.x = acc.x * inv + h4.x + s4.x;
    o.y = acc.y * inv + h4.y + s4.y;
    o.z = acc.z * inv + h4.z + s4.z;
    o.w = acc.w * inv + h4.w + s4.w;
    if (do_relu) {
        o.x = fmaxf(o.x, 0.f); o.y = fmaxf(o.y, 0.f);
        o.z = fmaxf(o.z, 0.f); o.w = fmaxf(o.w, 0.f);
    }
    *(float4*)&out[(size_t)i * DD + lane * 4] = o;
}

// Writes layer-0 output into g_h (avoids passing symbol address from host)
__global__ __launch_bounds__(256)
void attn_kernel_to_gh(const float* __restrict__ h,
                       const int* __restrict__ nbr) {
    // thin wrapper: replicate attn_kernel body writing to g_h with ReLU
    int gwarp = (blockIdx.x * blockDim.x + threadIdx.x) >> 5;
    if (gwarp >= NN) return;
    const int lane = threadIdx.x & 31;
    const int i = gwarp;

    const float* Q = g_qkvs;
    const float* K = g_qkvs + NDSZ;
    const float* V = g_qkvs + 2 * NDSZ;
    const float* S = g_qkvs + 3 * NDSZ;

    float4 q4 = *(const float4*)&Q[(size_t)i * DD + lane * 4];
    q4.x *= 0.25f; q4.y *= 0.25f; q4.z *= 0.25f; q4.w *= 0.25f;

    float m = -1e30f;
    float z = 0.f;
    float4 acc = make_float4(0.f, 0.f, 0.f, 0.f);

    const int e0 = g_rowptr[i];
    const int e1 = g_rowptr[i + 1];

    int j = (e0 < e1) ? nbr[e0] : 0;
    for (int e = e0; e < e1; ++e) {
        int jn = (e + 1 < e1) ? nbr[e + 1] : 0;
        float4 k4 = *(const float4*)&K[(size_t)j * DD + lane * 4];
        float4 v4 = *(const float4*)&V[(size_t)j * DD + lane * 4];
        float d = q4.x * k4.x + q4.y * k4.y + q4.z * k4.z + q4.w * k4.w;
        d += __shfl_xor_sync(0xFFFFFFFFu, d, 1);
        d += __shfl_xor_sync(0xFFFFFFFFu, d, 2);

        float nm = fmaxf(m, d);
        float scale = __expf(m - nm);
        float p = __expf(d - nm);
        z = z * scale + p;

        acc.x = acc.x * scale + p * v4.x;
        acc.y = acc.y * scale + p * v4.y;
        acc.z = acc.z * scale + p * v4.z;
        acc.w = acc.w * scale + p * v4.w;
        m = nm;
        j = jn;
    }

    float inv = 1.f / z;
    float4 h4 = *(const float4*)&h[(size_t)i * DD + lane * 4];
    float4 s4 = *(const float4*)&S[(size_t)i * DD + lane * 4];
    float4 o;
    o.x = fmaxf(acc.x * inv + h4.x + s4.x, 0.f);
    o.y = fmaxf(acc.y * inv + h4.y + s4.y, 0.f);
    o.z = fmaxf(acc.z * inv + h4.z + s4.z, 0.f);
    o.w = fmaxf(acc.w * inv + h4.w + s4.w, 0.f);
    *(float4*)&g_h[(size_t)i * DD + lane * 4] = o;
}

// gemm reading A from g_h (layer 1)
__global__ __launch_bounds__(256)
void gemm_qkvs_kernel_gh(const float* __restrict__ Wq, const float* __restrict__ Wk,
                         const float* __restrict__ Wv, const float* __restrict__ Ws,
                         const float* __restrict__ bq, const float* __restrict__ bk,
                         const float* __restrict__ bv, const float* __restrict__ bs,
                         int layer) {
    __shared__ float Asm[BK][BM + 4];
    __shared__ float Bsm[BK][BN];

    const float* A = g_h;
    const int mtx = blockIdx.y >> 1;
    const float* W = (mtx == 0 ? Wq : mtx == 1 ? Wk : mtx == 2 ? Wv : Ws)
                     + (size_t)layer * DD * DD;
    const float* bias = (mtx == 0 ? bq : mtx == 1 ? bk : mtx == 2 ? bv : bs)
                        + layer * DD;
    const int colbase = (blockIdx.y & 1) * BN;
    const int rowbase = blockIdx.x * BM;

    const int tid = threadIdx.x;
    const int tx = tid & 15;
    const int ty = tid >> 4;

    float acc[4][4] = {};

    for (int k0 = 0; k0 < DD; k0 += BK) {
        #pragma unroll
        for (int r = 0; r < 4; ++r) {
            int row = (tid >> 4) + r * 16;
            int grow = rowbase + row;
            float v = (grow < NN) ? A[(size_t)grow * DD + k0 + (tid & 15)] : 0.f;
            Asm[tid & 15][row] = v;
        }
        #pragma unroll
        for (int r = 0; r < 4; ++r) {
            int kk = (tid >> 6) + r * 4;
            int col = tid & 63;
            Bsm[kk][col] = W[(size_t)(k0 + kk) * DD + colbase + col];
        }
        __syncthreads();

        #pragma unroll
        for (int kk = 0; kk < BK; ++kk) {
            float a[4], b[4];
            *(float4*)a = *(const float4*)&Asm[kk][ty * 4];
            *(float4*)b = *(const float4*)&Bsm[kk][tx * 4];
            #pragma unroll
            for (int i2 = 0; i2 < 4; ++i2)
                #pragma unroll
                for (int j2 = 0; j2 < 4; ++j2)
                    acc[i2][j2] += a[i2] * b[j2];
        }
        __syncthreads();
    }

    float4 bvec;
    {
        const float* bp = bias + colbase + tx * 4;
        bvec.x = bp[0]; bvec.y = bp[1]; bvec.z = bp[2]; bvec.w = bp[3];
    }
    #pragma unroll
    for (int i2 = 0; i2 < 4; ++i2) {
        int grow = rowbase + ty * 4 + i2;
        if (grow < NN) {
            float4 o;
            o.x = acc[i2][0] + bvec.x;
            o.y = acc[i2][1] + bvec.y;
            o.z = acc[i2][2] + bvec.z;
            o.w = acc[i2][3] + bvec.w;
            *(float4*)&g_qkvs[(size_t)mtx * NDSZ + (size_t)grow * DD + colbase + tx * 4] = o;
        }
    }
}

// Final attention reading h from g_h, writing to d_out (no ReLU)
__global__ __launch_bounds__(256)
void attn_kernel_final(const int* __restrict__ nbr, float* __restrict__ out) {
    int gwarp = (blockIdx.x * blockDim.x + threadIdx.x) >> 5;
    if (gwarp >= NN) return;
    const int lane = threadIdx.x & 31;
    const int i = gwarp;

    const float* Q = g_qkvs;
    const float* K = g_qkvs + NDSZ;
    const float* V = g_qkvs + 2 * NDSZ;
    const float* S = g_qkvs + 3 * NDSZ;

    float4 q4 = *(const float4*)&Q[(size_t)i * DD + lane * 4];
    q4.x *= 0.25f; q4.y *= 0.25f; q4.z *= 0.25f; q4.w *= 0.25f;

    float m = -1e30f;
    float z = 0.f;
    float4 acc = make_float4(0.f, 0.f, 0.f, 0.f);

    const int e0 = g_rowptr[i];
    const int e1 = g_rowptr[i + 1];

    int j = (e0 < e1) ? nbr[e0] : 0;
    for (int e = e0; e < e1; ++e) {
        int jn = (e + 1 < e1) ? nbr[e + 1] : 0;
        float4 k4 = *(const float4*)&K[(size_t)j * DD + lane * 4];
        float4 v4 = *(const float4*)&V[(size_t)j * DD + lane * 4];
        float d = q4.x * k4.x + q4.y * k4.y + q4.z * k4.z + q4.w * k4.w;
        d += __shfl_xor_sync(0xFFFFFFFFu, d, 1);
        d += __shfl_xor_sync(0xFFFFFFFFu, d, 2);

        float nm = fmaxf(m, d);
        float scale = __expf(m - nm);
        float p = __expf(d - nm);
        z = z * scale + p;

        acc.x = acc.x * scale + p * v4.x;
        acc.y = acc.y * scale + p * v4.y;
        acc.z = acc.z * scale + p * v4.z;
        acc.w = acc.w * scale + p * v4.w;
        m = nm;
        j = jn;
    }

    float inv = 1.f / z;
    float4 h4 = *(const float4*)&g_h[(size_t)i * DD + lane * 4];
    float4 s4 = *(const float4*)&S[(size_t)i * DD + lane * 4];
    float4 o;
    o.x = acc.x * inv + h4.x + s4.x;
    o.y = acc.y * inv + h4.y + s4.y;
    o.z = acc.z * inv + h4.z + s4.z;
    o.w = acc.w * inv + h4.w + s4.w;
    *(float4*)&out[(size_t)i * DD + lane * 4] = o;
}

// ---------------------------------------------------------------------------
// Launch — ONLY kernel launches, zero other runtime API calls.
// Inputs: 0=x 1=Wq 2=bq 3=Wk 4=bk 5=Wv 6=bv 7=Ws 8=bs 9=attn_window[2,E] int32
// ---------------------------------------------------------------------------
extern "C" void kernel_launch(void* const* d_in, const int* in_sizes, int n_in,
                              void* d_out, int out_size) {
    const float* x  = (const float*)d_in[0];
    const float* Wq = (const float*)d_in[1];
    const float* bq = (const float*)d_in[2];
    const float* Wk = (const float*)d_in[3];
    const float* bk = (const float*)d_in[4];
    const float* Wv = (const float*)d_in[5];
    const float* bv = (const float*)d_in[6];
    const float* Ws = (const float*)d_in[7];
    const float* bs = (const float*)d_in[8];
    const int*   aw = (const int*)d_in[9];
    const int E = in_sizes[9] / 2;
    const int* src = aw;
    const int* dst = aw + E;

    build_rowptr_kernel<<<(NN + 256) / 256, 256>>>(src, E);

    dim3 ggrid((NN + BM - 1) / BM, 8);
    dim3 agrid((NN * 32 + 255) / 256);

    // Layer 0
    gemm_qkvs_kernel<<<ggrid, 256>>>(x, Wq, Wk, Wv, Ws, bq, bk, bv, bs, 0);
    attn_kernel_to_gh<<<agrid, 256>>>(x, dst);

    // Layer 1
    gemm_qkvs_kernel_gh<<<ggrid, 256>>>(Wq, Wk, Wv, Ws, bq, bk, bv, bs, 1);
    attn_kernel_final<<<agrid, 256>>>(dst, (float*)d_out);
}